// round 14
// baseline (speedup 1.0000x reference)
#include <cuda_runtime.h>
#include <cuda_fp16.h>
#include <math.h>

#define Nn 500000
#define Ee 16000000
#define Gg 5000
#define DIMc 10
#define FINc 64
#define RSTRIDE 16                                 // halves per feature row (32 B)
#define CSTR 128                                   // fixed CSR slots per node
#define DEGMAX (CSTR - 8)
#define EBLK (Ee / 2 / 256)                        // 31250 scatter blocks
#define PBLK (Nn * 8 / 256)                        // 15625 projection blocks

// ---------- static device scratch (all state returns to initial value each call) ----------
__device__ __align__(16) __half g_ha[((size_t)Nn + 1) * RSTRIDE];
__device__ __align__(16) __half g_hb[((size_t)Nn + 1) * RSTRIDE];
__device__ int   g_cursor[Nn + 1];                 // zero before build; re-zeroed in permb
__device__ __align__(16) int g_csr[((size_t)Nn + 1) * CSTR];
__device__ int   g_perm[Nn];                       // node id | (deg << 20)
__device__ int   g_dbin[256];                      // zero; re-zeroed in scan
__device__ int   g_dcur[256];                      // recomputed every call
__device__ float g_sacc[Gg];                       // zero; re-zeroed in final
__device__ float g_cnt[Gg];                        // zero; re-zeroed in final

// ---------- helpers ----------
__device__ __forceinline__ void hadd4(uint4& a, const uint4 b) {
    *reinterpret_cast<__half2*>(&a.x) = __hadd2(*reinterpret_cast<const __half2*>(&a.x),
                                                *reinterpret_cast<const __half2*>(&b.x));
    *reinterpret_cast<__half2*>(&a.y) = __hadd2(*reinterpret_cast<const __half2*>(&a.y),
                                                *reinterpret_cast<const __half2*>(&b.y));
    *reinterpret_cast<__half2*>(&a.z) = __hadd2(*reinterpret_cast<const __half2*>(&a.z),
                                                *reinterpret_cast<const __half2*>(&b.z));
    *reinterpret_cast<__half2*>(&a.w) = __hadd2(*reinterpret_cast<const __half2*>(&a.w),
                                                *reinterpret_cast<const __half2*>(&b.w));
}

__device__ __forceinline__ void add8(float* acc, uint4 v) {
    float2 f;
    f = __half22float2(*reinterpret_cast<__half2*>(&v.x)); acc[0] += f.x; acc[1] += f.y;
    f = __half22float2(*reinterpret_cast<__half2*>(&v.y)); acc[2] += f.x; acc[3] += f.y;
    f = __half22float2(*reinterpret_cast<__half2*>(&v.z)); acc[4] += f.x; acc[5] += f.y;
    f = __half22float2(*reinterpret_cast<__half2*>(&v.w)); acc[6] += f.x; acc[7] += f.y;
}

__device__ __forceinline__ void store_row10(__half* row, const float* y) {
    __half2 p0 = __floats2half2_rn(y[0], y[1]);
    __half2 p1 = __floats2half2_rn(y[2], y[3]);
    __half2 p2 = __floats2half2_rn(y[4], y[5]);
    __half2 p3 = __floats2half2_rn(y[6], y[7]);
    __half2 p4 = __floats2half2_rn(y[8], y[9]);
    uint4 o;
    o.x = *reinterpret_cast<unsigned*>(&p0);
    o.y = *reinterpret_cast<unsigned*>(&p1);
    o.z = *reinterpret_cast<unsigned*>(&p2);
    o.w = *reinterpret_cast<unsigned*>(&p3);
    *reinterpret_cast<uint4*>(row) = o;
    *reinterpret_cast<unsigned*>(row + 8) = *reinterpret_cast<unsigned*>(&p4);
}

// ---------- 1: build = scatter (blocks < EBLK) + projection (blocks >= EBLK) ----------
// Scatter is L2-RMW-bound; projection is DRAM/FMA-bound. Co-resident blocks overlap them.
__global__ void k_build(const int* __restrict__ src, const int* __restrict__ dst,
                        const float* __restrict__ h, const float* __restrict__ W1,
                        const int* __restrict__ ng) {
    if (blockIdx.x < EBLK) {
        // ---- scatter: 2 edges/thread into fixed-stride CSR ----
        int e2 = blockIdx.x * blockDim.x + threadIdx.x;
        int2 d = __ldg(reinterpret_cast<const int2*>(dst) + e2);
        int2 s = __ldg(reinterpret_cast<const int2*>(src) + e2);
        int p0 = atomicAdd(&g_cursor[d.x], 1);
        g_csr[(size_t)d.x * CSTR + min(p0, CSTR - 1)] = s.x;
        int p1 = atomicAdd(&g_cursor[d.y], 1);
        g_csr[(size_t)d.y * CSTR + min(p1, CSTR - 1)] = s.y;
    } else {
        // ---- projection: y1 = h @ W1_1 (8 lanes/node) + graph counts ----
        __shared__ float sW[FINc * DIMc];
        for (int t = threadIdx.x; t < FINc * DIMc; t += blockDim.x) sW[t] = W1[t];
        __syncthreads();

        int gtid = (blockIdx.x - EBLK) * blockDim.x + threadIdx.x;
        int i = gtid >> 3;
        int sub8 = gtid & 7;

        const float4* hp = reinterpret_cast<const float4*>(h + (size_t)i * FINc + sub8 * 8);
        float4 a = __ldg(hp);
        float4 b = __ldg(hp + 1);

        float acc[DIMc];
        const float* w = sW + (sub8 * 8) * DIMc;
        #pragma unroll
        for (int j = 0; j < DIMc; j++) {
            float v;
            v  = a.x * w[0 * DIMc + j];
            v += a.y * w[1 * DIMc + j];
            v += a.z * w[2 * DIMc + j];
            v += a.w * w[3 * DIMc + j];
            v += b.x * w[4 * DIMc + j];
            v += b.y * w[5 * DIMc + j];
            v += b.z * w[6 * DIMc + j];
            v += b.w * w[7 * DIMc + j];
            acc[j] = v;
        }
        #pragma unroll
        for (int off = 4; off > 0; off >>= 1) {
            #pragma unroll
            for (int j = 0; j < DIMc; j++)
                acc[j] += __shfl_down_sync(0xffffffffu, acc[j], off, 8);
        }

        if (sub8 == 0) {
            store_row10(g_ha + (size_t)i * RSTRIDE, acc);
            atomicAdd(&g_cnt[ng[i]], 1.0f);
        }
    }
}

// ---------- 2: per-node post: pad CSR rows to mult of 8 + degree-bin histogram ----------
__global__ void k_post() {
    __shared__ int shist[256];
    int t = threadIdx.x;                 // blockDim == 256
    shist[t] = 0;
    __syncthreads();
    int i = blockIdx.x * blockDim.x + t;
    if (i < Nn) {
        int d = min(g_cursor[i], DEGMAX);
        atomicAdd(&shist[d], 1);
        int pd = (d + 7) & ~7;
        size_t base = (size_t)i * CSTR;
        for (int q = d; q < pd; q++) g_csr[base + q] = Nn;   // dummy zero row
    }
    __syncthreads();
    if (shist[t]) atomicAdd(&g_dbin[t], shist[t]);
}

// ---------- 3: tiny scan: descending-degree (LPT) bucket bases; recycles dbin ----------
__global__ void k_scan() {
    __shared__ int sb[256];
    int t = threadIdx.x;
    int v = g_dbin[t];
    sb[t] = v;
    __syncthreads();
    #pragma unroll
    for (int off = 1; off < 256; off <<= 1) {
        int q = (t >= off) ? sb[t - off] : 0;
        __syncthreads();
        sb[t] += q;
        __syncthreads();
    }
    g_dcur[t] = sb[255] - sb[t];         // heavy nodes first
    g_dbin[t] = 0;                       // reset for next call
}

// ---------- 4: perm build (deg packed) + cursor reset ----------
__global__ void k_permb() {
    int i = blockIdx.x * blockDim.x + threadIdx.x;
    if (i < Nn) {
        int d = min(g_cursor[i], DEGMAX);
        g_cursor[i] = 0;                              // reset for next call
        int r = atomicAdd(&g_dcur[d], 1);
        g_perm[r] = i | (d << 20);                    // pack degree
    }
}

// ---------- 5-9: fused layer: pair gather + full-warp MLP (at L1tex wavefront floor) ----------
template <int PING, bool LAST>
__global__ void __launch_bounds__(256, 6) k_layer(
        const float* __restrict__ b1, const float* __restrict__ W2,
        const float* __restrict__ b2, const float* __restrict__ l,
        const float* __restrict__ W1n, const int* __restrict__ ng) {
    const __half* __restrict__ yin = (PING == 0) ? g_ha : g_hb;
    __half* __restrict__       yout = (PING == 0) ? g_hb : g_ha;

    __shared__ float sW2[DIMc * DIMc], sW1n[DIMc * DIMc], sb1[DIMc], sb2[DIMc], sl[DIMc];
    __shared__ float sacc[8][32][13];    // [warp][node][dim]; stride 13: conflict-free
    int t = threadIdx.x;
    if (t < DIMc * DIMc) {
        sW2[t] = W2[t];
        if (!LAST) sW1n[t] = W1n[t];
    }
    if (t < DIMc) { sb1[t] = b1[t]; sb2[t] = b2[t]; sl[t] = l[t]; }
    __syncthreads();

    int lane = t & 31;
    int wid = t >> 5;
    int warp_global = (blockIdx.x * blockDim.x + t) >> 5;
    int idx_base = warp_global * 32;
    if (idx_base >= Nn) return;          // Nn % 32 == 0: full warps only

    int sub = lane & 1;
    const int baselane = lane & ~1;

    // ---- gather phase: two 16-node halves, pair-per-node, r[4] staging ----
    #pragma unroll 1
    for (int hh = 0; hh < 2; hh++) {
        int nw = hh * 16 + (lane >> 1);
        int pv = __ldg(&g_perm[idx_base + nw]);
        int i = pv & 0xFFFFF;
        int deg = pv >> 20;

        size_t e0 = (size_t)i * CSTR;
        int iters = (deg + 7) >> 3;
        int itersW = __reduce_max_sync(0xffffffffu, iters);

        float acc[8] = {0, 0, 0, 0, 0, 0, 0, 0};
        add8(acc, __ldg(reinterpret_cast<const uint4*>(yin + (size_t)i * RSTRIDE + sub * 8)));

        const size_t cbase = e0 + sub * 4;
        for (int it = 0; it < itersW; ++it) {
            bool live = (it < iters);
            size_t cidx = live ? (cbase + (size_t)it * 8) : ((size_t)Nn * CSTR);
            int4 idv = __ldg(reinterpret_cast<const int4*>(g_csr + cidx));
            int id[4] = {idv.x, idv.y, idv.z, idv.w};

            #pragma unroll
            for (int c = 0; c < 2; c++) {
                uint4 r[4];
                #pragma unroll
                for (int k = 0; k < 4; ++k) {
                    int s = __shfl_sync(0xffffffffu, id[k], baselane + c);
                    if (!live) s = Nn;
                    r[k] = __ldg(reinterpret_cast<const uint4*>(
                            yin + (size_t)s * RSTRIDE + sub * 8));
                }
                hadd4(r[0], r[1]);
                hadd4(r[2], r[3]);
                hadd4(r[0], r[2]);
                add8(acc, r[0]);
            }
        }

        if (sub == 0) {
            #pragma unroll
            for (int j = 0; j < 8; j++) sacc[wid][nw][j] = acc[j];
        } else {
            sacc[wid][nw][8] = acc[0];
            sacc[wid][nw][9] = acc[1];
        }
    }
    __syncwarp();

    // ---- MLP phase: one node per lane (32 nodes per warp) ----
    int pv = __ldg(&g_perm[idx_base + lane]);
    int i = pv & 0xFFFFF;

    float u[DIMc];
    #pragma unroll
    for (int j = 0; j < DIMc; j++)
        u[j] = fmaxf(sacc[wid][lane][j] + sb1[j], 0.0f);

    float x[DIMc];
    #pragma unroll
    for (int j = 0; j < DIMc; j++) {
        float tv = sb2[j];
        #pragma unroll
        for (int k = 0; k < DIMc; k++) tv += u[k] * sW2[k * DIMc + j];
        x[j] = fmaxf(tv, 0.0f);
    }

    float dot = 0.0f;
    #pragma unroll
    for (int j = 0; j < DIMc; j++) dot += x[j] * sl[j];
    atomicAdd(&g_sacc[__ldg(&ng[i])], dot);

    if (!LAST) {
        float yn[DIMc];
        #pragma unroll
        for (int j2 = 0; j2 < DIMc; j2++) {
            float v = 0.0f;
            #pragma unroll
            for (int j = 0; j < DIMc; j++) v += x[j] * sW1n[j * DIMc + j2];
            yn[j2] = v;
        }
        store_row10(yout + (size_t)i * RSTRIDE, yn);
    }
}

// ---------- 10: final (reads + resets accumulators) ----------
__global__ void k_final(float* __restrict__ out) {
    int g = blockIdx.x * blockDim.x + threadIdx.x;
    if (g < Gg) {
        float c = fmaxf(g_cnt[g], 1.0f);
        float s = g_sacc[g] / c;
        out[g] = 1.0f / (1.0f + expf(-s));
        g_sacc[g] = 0.0f;                 // reset for next call
        g_cnt[g] = 0.0f;
    }
}

extern "C" void kernel_launch(void* const* d_in, const int* in_sizes, int n_in,
                              void* d_out, int out_size) {
    const float* h   = (const float*)d_in[0];
    const int*   src = (const int*)d_in[1];
    const int*   dst = (const int*)d_in[2];
    const int*   ng  = (const int*)d_in[3];
    const float* W1[5]; const float* b1[5]; const float* W2[5];
    const float* b2[5]; const float* ll[5];
    for (int i = 0; i < 5; i++) {
        W1[i] = (const float*)d_in[4 + 5 * i + 0];
        b1[i] = (const float*)d_in[4 + 5 * i + 1];
        W2[i] = (const float*)d_in[4 + 5 * i + 2];
        b2[i] = (const float*)d_in[4 + 5 * i + 3];
        ll[i] = (const float*)d_in[4 + 5 * i + 4];
    }
    float* out = (float*)d_out;

    const int TB = 256;
    int nblk = (Nn + TB - 1) / TB;
    int gblk = (Gg + TB - 1) / TB;
    int lblk = (Nn + TB - 1) / TB;             // 1 thread per node (32 nodes / warp)

    k_build<<<EBLK + PBLK, TB>>>(src, dst, h, W1[0], ng);                     // 1
    k_post<<<nblk, TB>>>();                                                   // 2
    k_scan<<<1, 256>>>();                                                     // 3
    k_permb<<<nblk, TB>>>();                                                  // 4
    k_layer<0, false><<<lblk, TB>>>(b1[0], W2[0], b2[0], ll[0], W1[1], ng);   // 5
    k_layer<1, false><<<lblk, TB>>>(b1[1], W2[1], b2[1], ll[1], W1[2], ng);   // 6 <- profiled
    k_layer<0, false><<<lblk, TB>>>(b1[2], W2[2], b2[2], ll[2], W1[3], ng);   // 7
    k_layer<1, false><<<lblk, TB>>>(b1[3], W2[3], b2[3], ll[3], W1[4], ng);   // 8
    k_layer<0, true ><<<lblk, TB>>>(b1[4], W2[4], b2[4], ll[4], nullptr, ng); // 9
    k_final<<<gblk, TB>>>(out);                                               // 10
}

// round 15
// speedup vs baseline: 1.1110x; 1.1110x over previous
#include <cuda_runtime.h>
#include <cuda_fp16.h>
#include <math.h>

#define Nn 500000
#define Ee 16000000
#define Gg 5000
#define DIMc 10
#define FINc 64
#define RSTRIDE 16                                 // halves per feature row (32 B)
#define CSTR 128                                   // fixed CSR slots per node
#define DEGMAX (CSTR - 8)
#define EBLK (Ee / 2 / 256)                        // 31250 scatter blocks
#define PBLK (Nn * 8 / 256)                        // 15625 projection blocks

// ---------- static device scratch (all state returns to initial value each call) ----------
__device__ __align__(16) __half g_ha[((size_t)Nn + 1) * RSTRIDE];
__device__ __align__(16) __half g_hb[((size_t)Nn + 1) * RSTRIDE];
__device__ int   g_cursor[Nn + 1];                 // zero before build; re-zeroed in post
__device__ __align__(16) int g_csr[((size_t)Nn + 1) * CSTR];
__device__ int   g_perm[Nn];                       // node id | (deg << 20)
__device__ int   g_rank[Nn];                       // global-bin rank | (deg << 20)
__device__ int   g_dbin[256];                      // zero; re-zeroed in scan
__device__ int   g_dcur[256];                      // bucket bases; recomputed every call
__device__ float g_sacc[Gg];                       // zero; re-zeroed in final
__device__ float g_cnt[Gg];                        // zero; re-zeroed in final

// ---------- helpers ----------
__device__ __forceinline__ void hadd4(uint4& a, const uint4 b) {
    *reinterpret_cast<__half2*>(&a.x) = __hadd2(*reinterpret_cast<const __half2*>(&a.x),
                                                *reinterpret_cast<const __half2*>(&b.x));
    *reinterpret_cast<__half2*>(&a.y) = __hadd2(*reinterpret_cast<const __half2*>(&a.y),
                                                *reinterpret_cast<const __half2*>(&b.y));
    *reinterpret_cast<__half2*>(&a.z) = __hadd2(*reinterpret_cast<const __half2*>(&a.z),
                                                *reinterpret_cast<const __half2*>(&b.z));
    *reinterpret_cast<__half2*>(&a.w) = __hadd2(*reinterpret_cast<const __half2*>(&a.w),
                                                *reinterpret_cast<const __half2*>(&b.w));
}

__device__ __forceinline__ void add8(float* acc, uint4 v) {
    float2 f;
    f = __half22float2(*reinterpret_cast<__half2*>(&v.x)); acc[0] += f.x; acc[1] += f.y;
    f = __half22float2(*reinterpret_cast<__half2*>(&v.y)); acc[2] += f.x; acc[3] += f.y;
    f = __half22float2(*reinterpret_cast<__half2*>(&v.z)); acc[4] += f.x; acc[5] += f.y;
    f = __half22float2(*reinterpret_cast<__half2*>(&v.w)); acc[6] += f.x; acc[7] += f.y;
}

__device__ __forceinline__ void store_row10(__half* row, const float* y) {
    __half2 p0 = __floats2half2_rn(y[0], y[1]);
    __half2 p1 = __floats2half2_rn(y[2], y[3]);
    __half2 p2 = __floats2half2_rn(y[4], y[5]);
    __half2 p3 = __floats2half2_rn(y[6], y[7]);
    __half2 p4 = __floats2half2_rn(y[8], y[9]);
    uint4 o;
    o.x = *reinterpret_cast<unsigned*>(&p0);
    o.y = *reinterpret_cast<unsigned*>(&p1);
    o.z = *reinterpret_cast<unsigned*>(&p2);
    o.w = *reinterpret_cast<unsigned*>(&p3);
    *reinterpret_cast<uint4*>(row) = o;
    *reinterpret_cast<unsigned*>(row + 8) = *reinterpret_cast<unsigned*>(&p4);
}

// ---------- 1: build = scatter (blocks < EBLK) + projection (blocks >= EBLK) ----------
__global__ void k_build(const int* __restrict__ src, const int* __restrict__ dst,
                        const float* __restrict__ h, const float* __restrict__ W1,
                        const int* __restrict__ ng) {
    if (blockIdx.x < EBLK) {
        int e2 = blockIdx.x * blockDim.x + threadIdx.x;
        int2 d = __ldg(reinterpret_cast<const int2*>(dst) + e2);
        int2 s = __ldg(reinterpret_cast<const int2*>(src) + e2);
        int p0 = atomicAdd(&g_cursor[d.x], 1);
        g_csr[(size_t)d.x * CSTR + min(p0, CSTR - 1)] = s.x;
        int p1 = atomicAdd(&g_cursor[d.y], 1);
        g_csr[(size_t)d.y * CSTR + min(p1, CSTR - 1)] = s.y;
    } else {
        __shared__ float sW[FINc * DIMc];
        for (int t = threadIdx.x; t < FINc * DIMc; t += blockDim.x) sW[t] = W1[t];
        __syncthreads();

        int gtid = (blockIdx.x - EBLK) * blockDim.x + threadIdx.x;
        int i = gtid >> 3;
        int sub8 = gtid & 7;

        const float4* hp = reinterpret_cast<const float4*>(h + (size_t)i * FINc + sub8 * 8);
        float4 a = __ldg(hp);
        float4 b = __ldg(hp + 1);

        float acc[DIMc];
        const float* w = sW + (sub8 * 8) * DIMc;
        #pragma unroll
        for (int j = 0; j < DIMc; j++) {
            float v;
            v  = a.x * w[0 * DIMc + j];
            v += a.y * w[1 * DIMc + j];
            v += a.z * w[2 * DIMc + j];
            v += a.w * w[3 * DIMc + j];
            v += b.x * w[4 * DIMc + j];
            v += b.y * w[5 * DIMc + j];
            v += b.z * w[6 * DIMc + j];
            v += b.w * w[7 * DIMc + j];
            acc[j] = v;
        }
        #pragma unroll
        for (int off = 4; off > 0; off >>= 1) {
            #pragma unroll
            for (int j = 0; j < DIMc; j++)
                acc[j] += __shfl_down_sync(0xffffffffu, acc[j], off, 8);
        }

        if (sub8 == 0) {
            store_row10(g_ha + (size_t)i * RSTRIDE, acc);
            atomicAdd(&g_cnt[ng[i]], 1.0f);
        }
    }
}

// ---------- 2: post: pad CSR + hierarchical rank (shared atomics + 1 global atomic/bin) ----------
__global__ void k_post() {
    __shared__ int shist[256];           // local bin histogram / intra-rank counter
    __shared__ int sbase[256];           // this block's base within the global bin
    int t = threadIdx.x;                 // blockDim == 256
    shist[t] = 0;
    __syncthreads();
    int i = blockIdx.x * blockDim.x + t;
    int d = 0, intrarank = 0;
    if (i < Nn) {
        d = min(g_cursor[i], DEGMAX);
        g_cursor[i] = 0;                 // reset for next call
        intrarank = atomicAdd(&shist[d], 1);   // shared atomic: intra-block rank
        int pd = (d + 7) & ~7;
        size_t base = (size_t)i * CSTR;
        for (int q = d; q < pd; q++) g_csr[base + q] = Nn;   // dummy zero row
    }
    __syncthreads();
    if (shist[t]) sbase[t] = atomicAdd(&g_dbin[t], shist[t]);  // 1 global atomic per bin
    __syncthreads();
    if (i < Nn) g_rank[i] = (sbase[d] + intrarank) | (d << 20);
}

// ---------- 3: tiny scan: descending-degree (LPT) bucket bases; recycles dbin ----------
__global__ void k_scan() {
    __shared__ int sb[256];
    int t = threadIdx.x;
    int v = g_dbin[t];
    sb[t] = v;
    __syncthreads();
    #pragma unroll
    for (int off = 1; off < 256; off <<= 1) {
        int q = (t >= off) ? sb[t - off] : 0;
        __syncthreads();
        sb[t] += q;
        __syncthreads();
    }
    g_dcur[t] = sb[255] - sb[t];         // heavy nodes first
    g_dbin[t] = 0;                       // reset for next call
}

// ---------- 4: perm build: contention-free scattered write ----------
__global__ void k_permb() {
    int i = blockIdx.x * blockDim.x + threadIdx.x;
    if (i < Nn) {
        int rv = __ldg(&g_rank[i]);
        int rank = rv & 0xFFFFF;
        int d = rv >> 20;
        g_perm[g_dcur[d] + rank] = i | (d << 20);
    }
}

// ---------- 5-9: fused layer: pair gather + full-warp MLP (at L1tex wavefront floor) ----------
template <int PING, bool LAST>
__global__ void __launch_bounds__(256, 6) k_layer(
        const float* __restrict__ b1, const float* __restrict__ W2,
        const float* __restrict__ b2, const float* __restrict__ l,
        const float* __restrict__ W1n, const int* __restrict__ ng) {
    const __half* __restrict__ yin = (PING == 0) ? g_ha : g_hb;
    __half* __restrict__       yout = (PING == 0) ? g_hb : g_ha;

    __shared__ float sW2[DIMc * DIMc], sW1n[DIMc * DIMc], sb1[DIMc], sb2[DIMc], sl[DIMc];
    __shared__ float sacc[8][32][13];    // [warp][node][dim]; stride 13: conflict-free
    int t = threadIdx.x;
    if (t < DIMc * DIMc) {
        sW2[t] = W2[t];
        if (!LAST) sW1n[t] = W1n[t];
    }
    if (t < DIMc) { sb1[t] = b1[t]; sb2[t] = b2[t]; sl[t] = l[t]; }
    __syncthreads();

    int lane = t & 31;
    int wid = t >> 5;
    int warp_global = (blockIdx.x * blockDim.x + t) >> 5;
    int idx_base = warp_global * 32;
    if (idx_base >= Nn) return;          // Nn % 32 == 0: full warps only

    int sub = lane & 1;
    const int baselane = lane & ~1;

    // ---- gather phase: two 16-node halves, pair-per-node ----
    #pragma unroll 1
    for (int hh = 0; hh < 2; hh++) {
        int nw = hh * 16 + (lane >> 1);
        int pv = __ldg(&g_perm[idx_base + nw]);
        int i = pv & 0xFFFFF;
        int deg = pv >> 20;

        size_t e0 = (size_t)i * CSTR;
        int iters = (deg + 7) >> 3;
        int itersW = __reduce_max_sync(0xffffffffu, iters);

        float acc[8] = {0, 0, 0, 0, 0, 0, 0, 0};
        add8(acc, __ldg(reinterpret_cast<const uint4*>(yin + (size_t)i * RSTRIDE + sub * 8)));

        const size_t cbase = e0 + sub * 4;
        for (int it = 0; it < itersW; ++it) {
            bool live = (it < iters);
            size_t cidx = live ? (cbase + (size_t)it * 8) : ((size_t)Nn * CSTR);
            int4 idv = __ldg(reinterpret_cast<const int4*>(g_csr + cidx));
            int id[4] = {idv.x, idv.y, idv.z, idv.w};

            #pragma unroll
            for (int c = 0; c < 2; c++) {
                uint4 r[4];
                #pragma unroll
                for (int k = 0; k < 4; ++k) {
                    int s = __shfl_sync(0xffffffffu, id[k], baselane + c);
                    if (!live) s = Nn;
                    r[k] = __ldg(reinterpret_cast<const uint4*>(
                            yin + (size_t)s * RSTRIDE + sub * 8));
                }
                hadd4(r[0], r[1]);
                hadd4(r[2], r[3]);
                hadd4(r[0], r[2]);
                add8(acc, r[0]);
            }
        }

        if (sub == 0) {
            #pragma unroll
            for (int j = 0; j < 8; j++) sacc[wid][nw][j] = acc[j];
        } else {
            sacc[wid][nw][8] = acc[0];
            sacc[wid][nw][9] = acc[1];
        }
    }
    __syncwarp();

    // ---- MLP phase: one node per lane (32 nodes per warp) ----
    int pv = __ldg(&g_perm[idx_base + lane]);
    int i = pv & 0xFFFFF;

    float u[DIMc];
    #pragma unroll
    for (int j = 0; j < DIMc; j++)
        u[j] = fmaxf(sacc[wid][lane][j] + sb1[j], 0.0f);

    float x[DIMc];
    #pragma unroll
    for (int j = 0; j < DIMc; j++) {
        float tv = sb2[j];
        #pragma unroll
        for (int k = 0; k < DIMc; k++) tv += u[k] * sW2[k * DIMc + j];
        x[j] = fmaxf(tv, 0.0f);
    }

    float dot = 0.0f;
    #pragma unroll
    for (int j = 0; j < DIMc; j++) dot += x[j] * sl[j];
    atomicAdd(&g_sacc[__ldg(&ng[i])], dot);

    if (!LAST) {
        float yn[DIMc];
        #pragma unroll
        for (int j2 = 0; j2 < DIMc; j2++) {
            float v = 0.0f;
            #pragma unroll
            for (int j = 0; j < DIMc; j++) v += x[j] * sW1n[j * DIMc + j2];
            yn[j2] = v;
        }
        store_row10(yout + (size_t)i * RSTRIDE, yn);
    }
}

// ---------- 10: final (reads + resets accumulators) ----------
__global__ void k_final(float* __restrict__ out) {
    int g = blockIdx.x * blockDim.x + threadIdx.x;
    if (g < Gg) {
        float c = fmaxf(g_cnt[g], 1.0f);
        float s = g_sacc[g] / c;
        out[g] = 1.0f / (1.0f + expf(-s));
        g_sacc[g] = 0.0f;                 // reset for next call
        g_cnt[g] = 0.0f;
    }
}

extern "C" void kernel_launch(void* const* d_in, const int* in_sizes, int n_in,
                              void* d_out, int out_size) {
    const float* h   = (const float*)d_in[0];
    const int*   src = (const int*)d_in[1];
    const int*   dst = (const int*)d_in[2];
    const int*   ng  = (const int*)d_in[3];
    const float* W1[5]; const float* b1[5]; const float* W2[5];
    const float* b2[5]; const float* ll[5];
    for (int i = 0; i < 5; i++) {
        W1[i] = (const float*)d_in[4 + 5 * i + 0];
        b1[i] = (const float*)d_in[4 + 5 * i + 1];
        W2[i] = (const float*)d_in[4 + 5 * i + 2];
        b2[i] = (const float*)d_in[4 + 5 * i + 3];
        ll[i] = (const float*)d_in[4 + 5 * i + 4];
    }
    float* out = (float*)d_out;

    const int TB = 256;
    int nblk = (Nn + TB - 1) / TB;
    int gblk = (Gg + TB - 1) / TB;
    int lblk = (Nn + TB - 1) / TB;             // 1 thread per node (32 nodes / warp)

    k_build<<<EBLK + PBLK, TB>>>(src, dst, h, W1[0], ng);                     // 1
    k_post<<<nblk, TB>>>();                                                   // 2
    k_scan<<<1, 256>>>();                                                     // 3
    k_permb<<<nblk, TB>>>();                                                  // 4
    k_layer<0, false><<<lblk, TB>>>(b1[0], W2[0], b2[0], ll[0], W1[1], ng);   // 5
    k_layer<1, false><<<lblk, TB>>>(b1[1], W2[1], b2[1], ll[1], W1[2], ng);   // 6 <- profiled
    k_layer<0, false><<<lblk, TB>>>(b1[2], W2[2], b2[2], ll[2], W1[3], ng);   // 7
    k_layer<1, false><<<lblk, TB>>>(b1[3], W2[3], b2[3], ll[3], W1[4], ng);   // 8
    k_layer<0, true ><<<lblk, TB>>>(b1[4], W2[4], b2[4], ll[4], nullptr, ng); // 9
    k_final<<<gblk, TB>>>(out);                                               // 10
}

// round 16
// speedup vs baseline: 1.1894x; 1.0705x over previous
#include <cuda_runtime.h>
#include <cuda_fp16.h>
#include <math.h>

#define Nn 500000
#define Ee 16000000
#define Gg 5000
#define DIMc 10
#define FINc 64
#define RSTRIDE 16                                 // halves per feature row (32 B)
#define CSTR 128                                   // fixed CSR slots per node
#define DEGMAX (CSTR - 8)
#define EBLK (Ee / 2 / 256)                        // 31250 scatter blocks
#define PBLK (Nn * 8 / 256)                        // 15625 projection blocks
// build grid: 46875 blocks, role-interleaved 2 scatter : 1 proj

// ---------- static device scratch (all state returns to initial value each call) ----------
__device__ __align__(16) __half g_ha[((size_t)Nn + 1) * RSTRIDE];
__device__ __align__(16) __half g_hb[((size_t)Nn + 1) * RSTRIDE];
__device__ int   g_cursor[Nn + 1];                 // zero before build; re-zeroed in post
__device__ __align__(16) int g_csr[((size_t)Nn + 1) * CSTR];
__device__ int   g_perm[Nn];                       // node id | (deg << 20)
__device__ int   g_rank[Nn];                       // global-bin rank | (deg << 20)
__device__ int   g_dbin[256];                      // zero; re-zeroed in scan
__device__ int   g_dcur[256];                      // bucket bases; recomputed every call
__device__ float g_sacc[Gg];                       // zero; re-zeroed in final
__device__ float g_cnt[Gg];                        // zero; re-zeroed in final

// ---------- helpers ----------
__device__ __forceinline__ void hadd4(uint4& a, const uint4 b) {
    *reinterpret_cast<__half2*>(&a.x) = __hadd2(*reinterpret_cast<const __half2*>(&a.x),
                                                *reinterpret_cast<const __half2*>(&b.x));
    *reinterpret_cast<__half2*>(&a.y) = __hadd2(*reinterpret_cast<const __half2*>(&a.y),
                                                *reinterpret_cast<const __half2*>(&b.y));
    *reinterpret_cast<__half2*>(&a.z) = __hadd2(*reinterpret_cast<const __half2*>(&a.z),
                                                *reinterpret_cast<const __half2*>(&b.z));
    *reinterpret_cast<__half2*>(&a.w) = __hadd2(*reinterpret_cast<const __half2*>(&a.w),
                                                *reinterpret_cast<const __half2*>(&b.w));
}

__device__ __forceinline__ void add8(float* acc, uint4 v) {
    float2 f;
    f = __half22float2(*reinterpret_cast<__half2*>(&v.x)); acc[0] += f.x; acc[1] += f.y;
    f = __half22float2(*reinterpret_cast<__half2*>(&v.y)); acc[2] += f.x; acc[3] += f.y;
    f = __half22float2(*reinterpret_cast<__half2*>(&v.z)); acc[4] += f.x; acc[5] += f.y;
    f = __half22float2(*reinterpret_cast<__half2*>(&v.w)); acc[6] += f.x; acc[7] += f.y;
}

__device__ __forceinline__ void store_row10(__half* row, const float* y) {
    __half2 p0 = __floats2half2_rn(y[0], y[1]);
    __half2 p1 = __floats2half2_rn(y[2], y[3]);
    __half2 p2 = __floats2half2_rn(y[4], y[5]);
    __half2 p3 = __floats2half2_rn(y[6], y[7]);
    __half2 p4 = __floats2half2_rn(y[8], y[9]);
    uint4 o;
    o.x = *reinterpret_cast<unsigned*>(&p0);
    o.y = *reinterpret_cast<unsigned*>(&p1);
    o.z = *reinterpret_cast<unsigned*>(&p2);
    o.w = *reinterpret_cast<unsigned*>(&p3);
    *reinterpret_cast<uint4*>(row) = o;
    *reinterpret_cast<unsigned*>(row + 8) = *reinterpret_cast<unsigned*>(&p4);
}

// ---------- 0: no-op (profiler slot alignment; removed once evidence lands) ----------
__global__ void k_nop() {}

// ---------- 1: build, role-interleaved: bid%3<2 -> scatter, bid%3==2 -> projection ----------
__global__ void k_build(const int* __restrict__ src, const int* __restrict__ dst,
                        const float* __restrict__ h, const float* __restrict__ W1,
                        const int* __restrict__ ng) {
    int bid = blockIdx.x;
    int r3 = bid % 3;
    if (r3 < 2) {
        // ---- scatter: 2 edges/thread into fixed-stride CSR ----
        int sbid = (bid / 3) * 2 + r3;             // 0..EBLK-1
        int e2 = sbid * blockDim.x + threadIdx.x;
        int2 d = __ldg(reinterpret_cast<const int2*>(dst) + e2);
        int2 s = __ldg(reinterpret_cast<const int2*>(src) + e2);
        int p0 = atomicAdd(&g_cursor[d.x], 1);
        g_csr[(size_t)d.x * CSTR + min(p0, CSTR - 1)] = s.x;
        int p1 = atomicAdd(&g_cursor[d.y], 1);
        g_csr[(size_t)d.y * CSTR + min(p1, CSTR - 1)] = s.y;
    } else {
        // ---- projection: y1 = h @ W1_1 (8 lanes/node) + graph counts ----
        __shared__ float sW[FINc * DIMc];
        for (int t = threadIdx.x; t < FINc * DIMc; t += blockDim.x) sW[t] = W1[t];
        __syncthreads();

        int pbid = bid / 3;                        // 0..PBLK-1
        int gtid = pbid * blockDim.x + threadIdx.x;
        int i = gtid >> 3;
        int sub8 = gtid & 7;

        const float4* hp = reinterpret_cast<const float4*>(h + (size_t)i * FINc + sub8 * 8);
        float4 a = __ldg(hp);
        float4 b = __ldg(hp + 1);

        float acc[DIMc];
        const float* w = sW + (sub8 * 8) * DIMc;
        #pragma unroll
        for (int j = 0; j < DIMc; j++) {
            float v;
            v  = a.x * w[0 * DIMc + j];
            v += a.y * w[1 * DIMc + j];
            v += a.z * w[2 * DIMc + j];
            v += a.w * w[3 * DIMc + j];
            v += b.x * w[4 * DIMc + j];
            v += b.y * w[5 * DIMc + j];
            v += b.z * w[6 * DIMc + j];
            v += b.w * w[7 * DIMc + j];
            acc[j] = v;
        }
        #pragma unroll
        for (int off = 4; off > 0; off >>= 1) {
            #pragma unroll
            for (int j = 0; j < DIMc; j++)
                acc[j] += __shfl_down_sync(0xffffffffu, acc[j], off, 8);
        }

        if (sub8 == 0) {
            store_row10(g_ha + (size_t)i * RSTRIDE, acc);
            atomicAdd(&g_cnt[ng[i]], 1.0f);
        }
    }
}

// ---------- 2: post: pad CSR + hierarchical rank (shared atomics + 1 global atomic/bin) ----------
__global__ void k_post() {
    __shared__ int shist[256];           // local bin histogram / intra-rank counter
    __shared__ int sbase[256];           // this block's base within the global bin
    int t = threadIdx.x;                 // blockDim == 256
    shist[t] = 0;
    __syncthreads();
    int i = blockIdx.x * blockDim.x + t;
    int d = 0, intrarank = 0;
    if (i < Nn) {
        d = min(g_cursor[i], DEGMAX);
        g_cursor[i] = 0;                 // reset for next call
        intrarank = atomicAdd(&shist[d], 1);   // shared atomic: intra-block rank
        int pd = (d + 7) & ~7;
        size_t base = (size_t)i * CSTR;
        for (int q = d; q < pd; q++) g_csr[base + q] = Nn;   // dummy zero row
    }
    __syncthreads();
    if (shist[t]) sbase[t] = atomicAdd(&g_dbin[t], shist[t]);  // 1 global atomic per bin
    __syncthreads();
    if (i < Nn) g_rank[i] = (sbase[d] + intrarank) | (d << 20);
}

// ---------- 3: tiny scan: descending-degree (LPT) bucket bases; recycles dbin ----------
__global__ void k_scan() {
    __shared__ int sb[256];
    int t = threadIdx.x;
    int v = g_dbin[t];
    sb[t] = v;
    __syncthreads();
    #pragma unroll
    for (int off = 1; off < 256; off <<= 1) {
        int q = (t >= off) ? sb[t - off] : 0;
        __syncthreads();
        sb[t] += q;
        __syncthreads();
    }
    g_dcur[t] = sb[255] - sb[t];         // heavy nodes first
    g_dbin[t] = 0;                       // reset for next call
}

// ---------- 4: perm build: contention-free scattered write ----------
__global__ void k_permb() {
    int i = blockIdx.x * blockDim.x + threadIdx.x;
    if (i < Nn) {
        int rv = __ldg(&g_rank[i]);
        int rank = rv & 0xFFFFF;
        int d = rv >> 20;
        g_perm[g_dcur[d] + rank] = i | (d << 20);
    }
}

// ---------- 5-9: fused layer: pair gather + full-warp MLP (at L1tex wavefront floor) ----------
template <int PING, bool LAST>
__global__ void __launch_bounds__(256, 6) k_layer(
        const float* __restrict__ b1, const float* __restrict__ W2,
        const float* __restrict__ b2, const float* __restrict__ l,
        const float* __restrict__ W1n, const int* __restrict__ ng) {
    const __half* __restrict__ yin = (PING == 0) ? g_ha : g_hb;
    __half* __restrict__       yout = (PING == 0) ? g_hb : g_ha;

    __shared__ float sW2[DIMc * DIMc], sW1n[DIMc * DIMc], sb1[DIMc], sb2[DIMc], sl[DIMc];
    __shared__ float sacc[8][32][13];    // [warp][node][dim]; stride 13: conflict-free
    int t = threadIdx.x;
    if (t < DIMc * DIMc) {
        sW2[t] = W2[t];
        if (!LAST) sW1n[t] = W1n[t];
    }
    if (t < DIMc) { sb1[t] = b1[t]; sb2[t] = b2[t]; sl[t] = l[t]; }
    __syncthreads();

    int lane = t & 31;
    int wid = t >> 5;
    int warp_global = (blockIdx.x * blockDim.x + t) >> 5;
    int idx_base = warp_global * 32;
    if (idx_base >= Nn) return;          // Nn % 32 == 0: full warps only

    int sub = lane & 1;
    const int baselane = lane & ~1;

    // ---- gather phase: two 16-node halves, pair-per-node ----
    #pragma unroll 1
    for (int hh = 0; hh < 2; hh++) {
        int nw = hh * 16 + (lane >> 1);
        int pv = __ldg(&g_perm[idx_base + nw]);
        int i = pv & 0xFFFFF;
        int deg = pv >> 20;

        size_t e0 = (size_t)i * CSTR;
        int iters = (deg + 7) >> 3;
        int itersW = __reduce_max_sync(0xffffffffu, iters);

        float acc[8] = {0, 0, 0, 0, 0, 0, 0, 0};
        add8(acc, __ldg(reinterpret_cast<const uint4*>(yin + (size_t)i * RSTRIDE + sub * 8)));

        const size_t cbase = e0 + sub * 4;
        for (int it = 0; it < itersW; ++it) {
            bool live = (it < iters);
            size_t cidx = live ? (cbase + (size_t)it * 8) : ((size_t)Nn * CSTR);
            int4 idv = __ldg(reinterpret_cast<const int4*>(g_csr + cidx));
            int id[4] = {idv.x, idv.y, idv.z, idv.w};

            #pragma unroll
            for (int c = 0; c < 2; c++) {
                uint4 r[4];
                #pragma unroll
                for (int k = 0; k < 4; ++k) {
                    int s = __shfl_sync(0xffffffffu, id[k], baselane + c);
                    if (!live) s = Nn;
                    r[k] = __ldg(reinterpret_cast<const uint4*>(
                            yin + (size_t)s * RSTRIDE + sub * 8));
                }
                hadd4(r[0], r[1]);
                hadd4(r[2], r[3]);
                hadd4(r[0], r[2]);
                add8(acc, r[0]);
            }
        }

        if (sub == 0) {
            #pragma unroll
            for (int j = 0; j < 8; j++) sacc[wid][nw][j] = acc[j];
        } else {
            sacc[wid][nw][8] = acc[0];
            sacc[wid][nw][9] = acc[1];
        }
    }
    __syncwarp();

    // ---- MLP phase: one node per lane (32 nodes per warp) ----
    int pv = __ldg(&g_perm[idx_base + lane]);
    int i = pv & 0xFFFFF;

    float u[DIMc];
    #pragma unroll
    for (int j = 0; j < DIMc; j++)
        u[j] = fmaxf(sacc[wid][lane][j] + sb1[j], 0.0f);

    float x[DIMc];
    #pragma unroll
    for (int j = 0; j < DIMc; j++) {
        float tv = sb2[j];
        #pragma unroll
        for (int k = 0; k < DIMc; k++) tv += u[k] * sW2[k * DIMc + j];
        x[j] = fmaxf(tv, 0.0f);
    }

    float dot = 0.0f;
    #pragma unroll
    for (int j = 0; j < DIMc; j++) dot += x[j] * sl[j];
    atomicAdd(&g_sacc[__ldg(&ng[i])], dot);

    if (!LAST) {
        float yn[DIMc];
        #pragma unroll
        for (int j2 = 0; j2 < DIMc; j2++) {
            float v = 0.0f;
            #pragma unroll
            for (int j = 0; j < DIMc; j++) v += x[j] * sW1n[j * DIMc + j2];
            yn[j2] = v;
        }
        store_row10(yout + (size_t)i * RSTRIDE, yn);
    }
}

// ---------- 10: final (reads + resets accumulators) ----------
__global__ void k_final(float* __restrict__ out) {
    int g = blockIdx.x * blockDim.x + threadIdx.x;
    if (g < Gg) {
        float c = fmaxf(g_cnt[g], 1.0f);
        float s = g_sacc[g] / c;
        out[g] = 1.0f / (1.0f + expf(-s));
        g_sacc[g] = 0.0f;                 // reset for next call
        g_cnt[g] = 0.0f;
    }
}

extern "C" void kernel_launch(void* const* d_in, const int* in_sizes, int n_in,
                              void* d_out, int out_size) {
    const float* h   = (const float*)d_in[0];
    const int*   src = (const int*)d_in[1];
    const int*   dst = (const int*)d_in[2];
    const int*   ng  = (const int*)d_in[3];
    const float* W1[5]; const float* b1[5]; const float* W2[5];
    const float* b2[5]; const float* ll[5];
    for (int i = 0; i < 5; i++) {
        W1[i] = (const float*)d_in[4 + 5 * i + 0];
        b1[i] = (const float*)d_in[4 + 5 * i + 1];
        W2[i] = (const float*)d_in[4 + 5 * i + 2];
        b2[i] = (const float*)d_in[4 + 5 * i + 3];
        ll[i] = (const float*)d_in[4 + 5 * i + 4];
    }
    float* out = (float*)d_out;

    const int TB = 256;
    int nblk = (Nn + TB - 1) / TB;
    int gblk = (Gg + TB - 1) / TB;
    int lblk = (Nn + TB - 1) / TB;             // 1 thread per node (32 nodes / warp)

    k_nop<<<1, 32>>>();                                                       // 1 (slot pad)
    k_nop<<<1, 32>>>();                                                       // 2 (slot pad)
    k_nop<<<1, 32>>>();                                                       // 3 (slot pad)
    k_build<<<EBLK + PBLK, TB>>>(src, dst, h, W1[0], ng);                     // 4 <- profiled
    k_post<<<nblk, TB>>>();                                                   // 5
    k_scan<<<1, 256>>>();                                                     // 6
    k_permb<<<nblk, TB>>>();                                                  // 7
    k_layer<0, false><<<lblk, TB>>>(b1[0], W2[0], b2[0], ll[0], W1[1], ng);   // 8
    k_layer<1, false><<<lblk, TB>>>(b1[1], W2[1], b2[1], ll[1], W1[2], ng);   // 9
    k_layer<0, false><<<lblk, TB>>>(b1[2], W2[2], b2[2], ll[2], W1[3], ng);   // 10
    k_layer<1, false><<<lblk, TB>>>(b1[3], W2[3], b2[3], ll[3], W1[4], ng);   // 11
    k_layer<0, true ><<<lblk, TB>>>(b1[4], W2[4], b2[4], ll[4], nullptr, ng); // 12
    k_final<<<gblk, TB>>>(out);                                               // 13
}

// round 17
// speedup vs baseline: 1.2020x; 1.0106x over previous
#include <cuda_runtime.h>
#include <cuda_fp16.h>
#include <math.h>

#define Nn 500000
#define Ee 16000000
#define Gg 5000
#define DIMc 10
#define FINc 64
#define RSTRIDE 16                                 // halves per feature row (32 B)
#define CSTR 128                                   // fixed CSR slots per node
#define DEGMAX (CSTR - 8)
#define SBLK (Ee / 4 / 256)                        // 15625 scatter blocks (4 edges/thread)
#define PBLK (Nn * 8 / 256)                        // 15625 projection blocks

// ---------- static device scratch (all state returns to initial value each call) ----------
__device__ __align__(16) __half g_ha[((size_t)Nn + 1) * RSTRIDE];
__device__ __align__(16) __half g_hb[((size_t)Nn + 1) * RSTRIDE];
__device__ int   g_cursor[Nn + 1];                 // zero before build; re-zeroed in post
__device__ __align__(16) int g_csr[((size_t)Nn + 1) * CSTR];
__device__ int   g_perm[Nn];                       // node id | (deg << 20)
__device__ int   g_rank[Nn];                       // global-bin rank | (deg << 20)
__device__ int   g_dbin[256];                      // zero; re-zeroed in scan
__device__ int   g_dcur[256];                      // bucket bases; recomputed every call
__device__ float g_sacc[Gg];                       // zero; re-zeroed in final
__device__ float g_cnt[Gg];                        // zero; re-zeroed in final

// ---------- helpers ----------
__device__ __forceinline__ void hadd4(uint4& a, const uint4 b) {
    *reinterpret_cast<__half2*>(&a.x) = __hadd2(*reinterpret_cast<const __half2*>(&a.x),
                                                *reinterpret_cast<const __half2*>(&b.x));
    *reinterpret_cast<__half2*>(&a.y) = __hadd2(*reinterpret_cast<const __half2*>(&a.y),
                                                *reinterpret_cast<const __half2*>(&b.y));
    *reinterpret_cast<__half2*>(&a.z) = __hadd2(*reinterpret_cast<const __half2*>(&a.z),
                                                *reinterpret_cast<const __half2*>(&b.z));
    *reinterpret_cast<__half2*>(&a.w) = __hadd2(*reinterpret_cast<const __half2*>(&a.w),
                                                *reinterpret_cast<const __half2*>(&b.w));
}

__device__ __forceinline__ void add8(float* acc, uint4 v) {
    float2 f;
    f = __half22float2(*reinterpret_cast<__half2*>(&v.x)); acc[0] += f.x; acc[1] += f.y;
    f = __half22float2(*reinterpret_cast<__half2*>(&v.y)); acc[2] += f.x; acc[3] += f.y;
    f = __half22float2(*reinterpret_cast<__half2*>(&v.z)); acc[4] += f.x; acc[5] += f.y;
    f = __half22float2(*reinterpret_cast<__half2*>(&v.w)); acc[6] += f.x; acc[7] += f.y;
}

__device__ __forceinline__ void store_row10(__half* row, const float* y) {
    __half2 p0 = __floats2half2_rn(y[0], y[1]);
    __half2 p1 = __floats2half2_rn(y[2], y[3]);
    __half2 p2 = __floats2half2_rn(y[4], y[5]);
    __half2 p3 = __floats2half2_rn(y[6], y[7]);
    __half2 p4 = __floats2half2_rn(y[8], y[9]);
    uint4 o;
    o.x = *reinterpret_cast<unsigned*>(&p0);
    o.y = *reinterpret_cast<unsigned*>(&p1);
    o.z = *reinterpret_cast<unsigned*>(&p2);
    o.w = *reinterpret_cast<unsigned*>(&p3);
    *reinterpret_cast<uint4*>(row) = o;
    *reinterpret_cast<unsigned*>(row + 8) = *reinterpret_cast<unsigned*>(&p4);
}

// ---------- 1: build, 1:1 interleaved: even bid -> scatter (4 edges/thread), odd -> proj ----------
__global__ void k_build(const int* __restrict__ src, const int* __restrict__ dst,
                        const float* __restrict__ h, const float* __restrict__ W1,
                        const int* __restrict__ ng) {
    int bid = blockIdx.x;
    if ((bid & 1) == 0) {
        // ---- scatter: 4 edges/thread, independent atomics (MLP 4) ----
        int e4 = (bid >> 1) * blockDim.x + threadIdx.x;
        int4 d = __ldg(reinterpret_cast<const int4*>(dst) + e4);
        int4 s = __ldg(reinterpret_cast<const int4*>(src) + e4);
        int p0 = atomicAdd(&g_cursor[d.x], 1);
        int p1 = atomicAdd(&g_cursor[d.y], 1);
        int p2 = atomicAdd(&g_cursor[d.z], 1);
        int p3 = atomicAdd(&g_cursor[d.w], 1);
        g_csr[(size_t)d.x * CSTR + min(p0, CSTR - 1)] = s.x;
        g_csr[(size_t)d.y * CSTR + min(p1, CSTR - 1)] = s.y;
        g_csr[(size_t)d.z * CSTR + min(p2, CSTR - 1)] = s.z;
        g_csr[(size_t)d.w * CSTR + min(p3, CSTR - 1)] = s.w;
    } else {
        // ---- projection: y1 = h @ W1_1 (8 lanes/node) + graph counts ----
        __shared__ float sW[FINc * DIMc];
        for (int t = threadIdx.x; t < FINc * DIMc; t += blockDim.x) sW[t] = W1[t];
        __syncthreads();

        int pbid = bid >> 1;                       // 0..PBLK-1
        int gtid = pbid * blockDim.x + threadIdx.x;
        int i = gtid >> 3;
        int sub8 = gtid & 7;

        const float4* hp = reinterpret_cast<const float4*>(h + (size_t)i * FINc + sub8 * 8);
        float4 a = __ldg(hp);
        float4 b = __ldg(hp + 1);

        float acc[DIMc];
        const float* w = sW + (sub8 * 8) * DIMc;
        #pragma unroll
        for (int j = 0; j < DIMc; j++) {
            float v;
            v  = a.x * w[0 * DIMc + j];
            v += a.y * w[1 * DIMc + j];
            v += a.z * w[2 * DIMc + j];
            v += a.w * w[3 * DIMc + j];
            v += b.x * w[4 * DIMc + j];
            v += b.y * w[5 * DIMc + j];
            v += b.z * w[6 * DIMc + j];
            v += b.w * w[7 * DIMc + j];
            acc[j] = v;
        }
        #pragma unroll
        for (int off = 4; off > 0; off >>= 1) {
            #pragma unroll
            for (int j = 0; j < DIMc; j++)
                acc[j] += __shfl_down_sync(0xffffffffu, acc[j], off, 8);
        }

        if (sub8 == 0) {
            store_row10(g_ha + (size_t)i * RSTRIDE, acc);
            atomicAdd(&g_cnt[ng[i]], 1.0f);
        }
    }
}

// ---------- 2: post: pad CSR + hierarchical rank (shared atomics + 1 global atomic/bin) ----------
__global__ void k_post() {
    __shared__ int shist[256];           // local bin histogram / intra-rank counter
    __shared__ int sbase[256];           // this block's base within the global bin
    int t = threadIdx.x;                 // blockDim == 256
    shist[t] = 0;
    __syncthreads();
    int i = blockIdx.x * blockDim.x + t;
    int d = 0, intrarank = 0;
    if (i < Nn) {
        d = min(g_cursor[i], DEGMAX);
        g_cursor[i] = 0;                 // reset for next call
        intrarank = atomicAdd(&shist[d], 1);   // shared atomic: intra-block rank
        int pd = (d + 7) & ~7;
        size_t base = (size_t)i * CSTR;
        for (int q = d; q < pd; q++) g_csr[base + q] = Nn;   // dummy zero row
    }
    __syncthreads();
    if (shist[t]) sbase[t] = atomicAdd(&g_dbin[t], shist[t]);  // 1 global atomic per bin
    __syncthreads();
    if (i < Nn) g_rank[i] = (sbase[d] + intrarank) | (d << 20);
}

// ---------- 3: tiny scan: descending-degree (LPT) bucket bases; recycles dbin ----------
__global__ void k_scan() {
    __shared__ int sb[256];
    int t = threadIdx.x;
    int v = g_dbin[t];
    sb[t] = v;
    __syncthreads();
    #pragma unroll
    for (int off = 1; off < 256; off <<= 1) {
        int q = (t >= off) ? sb[t - off] : 0;
        __syncthreads();
        sb[t] += q;
        __syncthreads();
    }
    g_dcur[t] = sb[255] - sb[t];         // heavy nodes first
    g_dbin[t] = 0;                       // reset for next call
}

// ---------- 4: perm build: contention-free scattered write ----------
__global__ void k_permb() {
    int i = blockIdx.x * blockDim.x + threadIdx.x;
    if (i < Nn) {
        int rv = __ldg(&g_rank[i]);
        int rank = rv & 0xFFFFF;
        int d = rv >> 20;
        g_perm[g_dcur[d] + rank] = i | (d << 20);
    }
}

// ---------- 5-9: fused layer: pair gather + full-warp MLP (at L1tex wavefront floor) ----------
template <int PING, bool LAST>
__global__ void __launch_bounds__(256, 6) k_layer(
        const float* __restrict__ b1, const float* __restrict__ W2,
        const float* __restrict__ b2, const float* __restrict__ l,
        const float* __restrict__ W1n, const int* __restrict__ ng) {
    const __half* __restrict__ yin = (PING == 0) ? g_ha : g_hb;
    __half* __restrict__       yout = (PING == 0) ? g_hb : g_ha;

    __shared__ float sW2[DIMc * DIMc], sW1n[DIMc * DIMc], sb1[DIMc], sb2[DIMc], sl[DIMc];
    __shared__ float sacc[8][32][13];    // [warp][node][dim]; stride 13: conflict-free
    int t = threadIdx.x;
    if (t < DIMc * DIMc) {
        sW2[t] = W2[t];
        if (!LAST) sW1n[t] = W1n[t];
    }
    if (t < DIMc) { sb1[t] = b1[t]; sb2[t] = b2[t]; sl[t] = l[t]; }
    __syncthreads();

    int lane = t & 31;
    int wid = t >> 5;
    int warp_global = (blockIdx.x * blockDim.x + t) >> 5;
    int idx_base = warp_global * 32;
    if (idx_base >= Nn) return;          // Nn % 32 == 0: full warps only

    int sub = lane & 1;
    const int baselane = lane & ~1;

    // ---- gather phase: two 16-node halves, pair-per-node ----
    #pragma unroll 1
    for (int hh = 0; hh < 2; hh++) {
        int nw = hh * 16 + (lane >> 1);
        int pv = __ldg(&g_perm[idx_base + nw]);
        int i = pv & 0xFFFFF;
        int deg = pv >> 20;

        size_t e0 = (size_t)i * CSTR;
        int iters = (deg + 7) >> 3;
        int itersW = __reduce_max_sync(0xffffffffu, iters);

        float acc[8] = {0, 0, 0, 0, 0, 0, 0, 0};
        add8(acc, __ldg(reinterpret_cast<const uint4*>(yin + (size_t)i * RSTRIDE + sub * 8)));

        const size_t cbase = e0 + sub * 4;
        for (int it = 0; it < itersW; ++it) {
            bool live = (it < iters);
            size_t cidx = live ? (cbase + (size_t)it * 8) : ((size_t)Nn * CSTR);
            int4 idv = __ldg(reinterpret_cast<const int4*>(g_csr + cidx));
            int id[4] = {idv.x, idv.y, idv.z, idv.w};

            #pragma unroll
            for (int c = 0; c < 2; c++) {
                uint4 r[4];
                #pragma unroll
                for (int k = 0; k < 4; ++k) {
                    int s = __shfl_sync(0xffffffffu, id[k], baselane + c);
                    if (!live) s = Nn;
                    r[k] = __ldg(reinterpret_cast<const uint4*>(
                            yin + (size_t)s * RSTRIDE + sub * 8));
                }
                hadd4(r[0], r[1]);
                hadd4(r[2], r[3]);
                hadd4(r[0], r[2]);
                add8(acc, r[0]);
            }
        }

        if (sub == 0) {
            #pragma unroll
            for (int j = 0; j < 8; j++) sacc[wid][nw][j] = acc[j];
        } else {
            sacc[wid][nw][8] = acc[0];
            sacc[wid][nw][9] = acc[1];
        }
    }
    __syncwarp();

    // ---- MLP phase: one node per lane (32 nodes per warp) ----
    int pv = __ldg(&g_perm[idx_base + lane]);
    int i = pv & 0xFFFFF;

    float u[DIMc];
    #pragma unroll
    for (int j = 0; j < DIMc; j++)
        u[j] = fmaxf(sacc[wid][lane][j] + sb1[j], 0.0f);

    float x[DIMc];
    #pragma unroll
    for (int j = 0; j < DIMc; j++) {
        float tv = sb2[j];
        #pragma unroll
        for (int k = 0; k < DIMc; k++) tv += u[k] * sW2[k * DIMc + j];
        x[j] = fmaxf(tv, 0.0f);
    }

    float dot = 0.0f;
    #pragma unroll
    for (int j = 0; j < DIMc; j++) dot += x[j] * sl[j];
    atomicAdd(&g_sacc[__ldg(&ng[i])], dot);

    if (!LAST) {
        float yn[DIMc];
        #pragma unroll
        for (int j2 = 0; j2 < DIMc; j2++) {
            float v = 0.0f;
            #pragma unroll
            for (int j = 0; j < DIMc; j++) v += x[j] * sW1n[j * DIMc + j2];
            yn[j2] = v;
        }
        store_row10(yout + (size_t)i * RSTRIDE, yn);
    }
}

// ---------- 10: final (reads + resets accumulators) ----------
__global__ void k_final(float* __restrict__ out) {
    int g = blockIdx.x * blockDim.x + threadIdx.x;
    if (g < Gg) {
        float c = fmaxf(g_cnt[g], 1.0f);
        float s = g_sacc[g] / c;
        out[g] = 1.0f / (1.0f + expf(-s));
        g_sacc[g] = 0.0f;                 // reset for next call
        g_cnt[g] = 0.0f;
    }
}

extern "C" void kernel_launch(void* const* d_in, const int* in_sizes, int n_in,
                              void* d_out, int out_size) {
    const float* h   = (const float*)d_in[0];
    const int*   src = (const int*)d_in[1];
    const int*   dst = (const int*)d_in[2];
    const int*   ng  = (const int*)d_in[3];
    const float* W1[5]; const float* b1[5]; const float* W2[5];
    const float* b2[5]; const float* ll[5];
    for (int i = 0; i < 5; i++) {
        W1[i] = (const float*)d_in[4 + 5 * i + 0];
        b1[i] = (const float*)d_in[4 + 5 * i + 1];
        W2[i] = (const float*)d_in[4 + 5 * i + 2];
        b2[i] = (const float*)d_in[4 + 5 * i + 3];
        ll[i] = (const float*)d_in[4 + 5 * i + 4];
    }
    float* out = (float*)d_out;

    const int TB = 256;
    int nblk = (Nn + TB - 1) / TB;
    int gblk = (Gg + TB - 1) / TB;
    int lblk = (Nn + TB - 1) / TB;             // 1 thread per node (32 nodes / warp)

    k_build<<<SBLK + PBLK, TB>>>(src, dst, h, W1[0], ng);                     // 1
    k_post<<<nblk, TB>>>();                                                   // 2
    k_scan<<<1, 256>>>();                                                     // 3
    k_permb<<<nblk, TB>>>();                                                  // 4
    k_layer<0, false><<<lblk, TB>>>(b1[0], W2[0], b2[0], ll[0], W1[1], ng);   // 5
    k_layer<1, false><<<lblk, TB>>>(b1[1], W2[1], b2[1], ll[1], W1[2], ng);   // 6
    k_layer<0, false><<<lblk, TB>>>(b1[2], W2[2], b2[2], ll[2], W1[3], ng);   // 7
    k_layer<1, false><<<lblk, TB>>>(b1[3], W2[3], b2[3], ll[3], W1[4], ng);   // 8
    k_layer<0, true ><<<lblk, TB>>>(b1[4], W2[4], b2[4], ll[4], nullptr, ng); // 9
    k_final<<<gblk, TB>>>(out);                                               // 10
}